// round 3
// baseline (speedup 1.0000x reference)
#include <cuda_runtime.h>
#include <cuda_bf16.h>

// SparseNonzeroAvgPooling, CSR-pull formulation:
//   1. count contributors per output row (int atomics)
//   2. exclusive-scan counts -> offsets
//   3. fill bucket[] with contributor in_rows (atomicAdd cursor)
//   4. pull-gather: each output row sums its contributors in registers,
//      scales by 1/max(cnt,1), stores once. No float atomics, no finalize.

#define C_CH      32
#define MAX_NOUT  262144          // >= 250,000
#define MAX_M     4194304         // >= 4,000,000
#define SCAN_BLK  256
#define MAX_NB    1024            // MAX_NOUT / SCAN_BLK

__device__ int g_counts  [MAX_NOUT];
__device__ int g_offsets [MAX_NOUT + 1];
__device__ int g_cursor  [MAX_NOUT];
__device__ int g_blocksum[MAX_NB];
__device__ int g_blockoff[MAX_NB];
__device__ int g_bucket  [MAX_M];

__device__ __forceinline__ float4 f4add(float4 a, float4 b) {
    a.x += b.x; a.y += b.y; a.z += b.z; a.w += b.w; return a;
}

// ---------------------------------------------------------------------------
__global__ void zero_counts_kernel(int n_out)
{
    int i = blockIdx.x * blockDim.x + threadIdx.x;
    int stride = gridDim.x * blockDim.x;
    for (int k = i; k < n_out; k += stride) g_counts[k] = 0;
}

// ---------------------------------------------------------------------------
__global__ void count_kernel(const int* __restrict__ out_map, int M)
{
    int i = blockIdx.x * blockDim.x + threadIdx.x;
    int stride = gridDim.x * blockDim.x;
    for (int m = i; m < M; m += stride) {
        int o = __ldg(out_map + m);
        asm volatile("red.global.add.s32 [%0], %1;"
                     :: "l"(&g_counts[o]), "r"(1) : "memory");
    }
}

// ---------------------------------------------------------------------------
// Scan pass A: per-block sums of counts (SCAN_BLK counts per block).
__global__ void scanA_kernel(int n_out)
{
    __shared__ int sh[SCAN_BLK];
    int t = threadIdx.x;
    int i = blockIdx.x * SCAN_BLK + t;
    sh[t] = (i < n_out) ? g_counts[i] : 0;
    __syncthreads();
    for (int d = SCAN_BLK / 2; d > 0; d >>= 1) {
        if (t < d) sh[t] += sh[t + d];
        __syncthreads();
    }
    if (t == 0) g_blocksum[blockIdx.x] = sh[0];
}

// Scan pass B: single block exclusive-scans up to MAX_NB block sums.
__global__ void scanB_kernel(int nb)
{
    __shared__ int sh[MAX_NB];
    int t = threadIdx.x;
    int v = (t < nb) ? g_blocksum[t] : 0;
    sh[t] = v;
    __syncthreads();
    for (int d = 1; d < MAX_NB; d <<= 1) {
        int x = (t >= d) ? sh[t - d] : 0;
        __syncthreads();
        sh[t] += x;
        __syncthreads();
    }
    if (t < nb) g_blockoff[t] = sh[t] - v;   // exclusive
}

// Scan pass C: intra-block exclusive scan + block offset -> offsets & cursor.
__global__ void scanC_kernel(int n_out, int M)
{
    __shared__ int sh[SCAN_BLK];
    int t = threadIdx.x;
    int i = blockIdx.x * SCAN_BLK + t;
    int c = (i < n_out) ? g_counts[i] : 0;
    sh[t] = c;
    __syncthreads();
    for (int d = 1; d < SCAN_BLK; d <<= 1) {
        int x = (t >= d) ? sh[t - d] : 0;
        __syncthreads();
        sh[t] += x;
        __syncthreads();
    }
    if (i < n_out) {
        int off = g_blockoff[blockIdx.x] + sh[t] - c;  // exclusive
        g_offsets[i] = off;
        g_cursor[i]  = off;
    }
    if (i == 0) g_offsets[n_out] = M;
}

// ---------------------------------------------------------------------------
__global__ void fill_kernel(const int* __restrict__ in_map,
                            const int* __restrict__ out_map, int M)
{
    int i = blockIdx.x * blockDim.x + threadIdx.x;
    int stride = gridDim.x * blockDim.x;
    for (int m = i; m < M; m += stride) {
        int o    = __ldg(out_map + m);
        int irow = __ldg(in_map  + m);
        int pos  = atomicAdd(&g_cursor[o], 1);
        g_bucket[pos] = irow;
    }
}

// ---------------------------------------------------------------------------
// Pull gather: 8 threads per output row; sub-thread s owns float4 column s.
// 4-way unrolled contributor loop for MLP; fused average; single store.
__global__ void gather_kernel(const float4* __restrict__ in_feats4,
                              float4*       __restrict__ out4,
                              int n_out)
{
    unsigned int t   = blockIdx.x * blockDim.x + threadIdx.x;
    unsigned int row = t >> 3;
    unsigned int sub = t & 7u;
    if (row >= (unsigned int)n_out) return;

    int start = __ldg(&g_offsets[row]);
    int end   = __ldg(&g_offsets[row + 1]);
    int cnt   = end - start;

    float4 a0 = make_float4(0.f, 0.f, 0.f, 0.f);
    float4 a1 = a0, a2 = a0, a3 = a0;

    int k = start;
    for (; k + 4 <= end; k += 4) {
        int r0 = __ldg(&g_bucket[k]);
        int r1 = __ldg(&g_bucket[k + 1]);
        int r2 = __ldg(&g_bucket[k + 2]);
        int r3 = __ldg(&g_bucket[k + 3]);
        a0 = f4add(a0, __ldg(in_feats4 + (size_t)r0 * 8 + sub));
        a1 = f4add(a1, __ldg(in_feats4 + (size_t)r1 * 8 + sub));
        a2 = f4add(a2, __ldg(in_feats4 + (size_t)r2 * 8 + sub));
        a3 = f4add(a3, __ldg(in_feats4 + (size_t)r3 * 8 + sub));
    }
    for (; k < end; k++) {
        int r0 = __ldg(&g_bucket[k]);
        a0 = f4add(a0, __ldg(in_feats4 + (size_t)r0 * 8 + sub));
    }

    float4 s = f4add(f4add(a0, a1), f4add(a2, a3));
    float inv = 1.0f / fmaxf((float)cnt, 1.0f);
    s.x *= inv; s.y *= inv; s.z *= inv; s.w *= inv;

    out4[(size_t)row * 8 + sub] = s;
}

// ---------------------------------------------------------------------------
extern "C" void kernel_launch(void* const* d_in, const int* in_sizes, int n_in,
                              void* d_out, int out_size)
{
    const float4* in_feats4 = (const float4*)d_in[0];
    const int*    in_map    = (const int*)d_in[1];
    const int*    out_map   = (const int*)d_in[2];

    int n_out = out_size / C_CH;
    int M     = in_sizes[1];

    float4* out4 = (float4*)d_out;

    int nb = (n_out + SCAN_BLK - 1) / SCAN_BLK;   // <= 1024

    // 1. zero counts
    zero_counts_kernel<<<512, 256>>>(n_out);

    // 2. count contributors
    count_kernel<<<4096, 256>>>(out_map, M);

    // 3. exclusive scan (3 passes)
    scanA_kernel<<<nb, SCAN_BLK>>>(n_out);
    scanB_kernel<<<1, MAX_NB>>>(nb);
    scanC_kernel<<<nb, SCAN_BLK>>>(n_out, M);

    // 4. fill buckets
    fill_kernel<<<4096, 256>>>(in_map, out_map, M);

    // 5. pull gather + fused average
    {
        long long total = (long long)n_out * 8;
        int blocks = (int)((total + 255) / 256);
        gather_kernel<<<blocks, 256>>>(in_feats4, out4, n_out);
    }
}